// round 11
// baseline (speedup 1.0000x reference)
#include <cuda_runtime.h>
#include <math_constants.h>

#define BB 64
#define CC 256
#define HW 4096
#define CS 64
#define NC 8
#define NPART (BB * CC * 4)   // 4 partial blocks per channel

// ---- scratch (no allocations allowed) ----
__device__ float g_psum[NPART];
__device__ float g_pmin[NPART];
__device__ float g_pmax[NPART];
__device__ float g_mean[BB * CC];
__device__ float g_min[BB * CC];
__device__ float g_max[BB * CC];
__device__ float g_scale[BB * CC];
__device__ float g_smin[BB];
__device__ float g_smax[BB];
__device__ float g_s[BB];
__device__ float g_z[BB];

// ------------------------------------------------------------------
// Kernel 1a: partial sum/min/max. EXACTLY k_quant's launch shape:
// 65536 blocks x 256 threads, ONE float4 per thread, fast block
// turnover. Each block covers 256 consecutive float4 = 1/4 channel.
// ------------------------------------------------------------------
__global__ void __launch_bounds__(256) k_stat1(const float* __restrict__ x) {
    int i = blockIdx.x * 256 + threadIdx.x;   // global float4 index
    float4 v = __ldg(reinterpret_cast<const float4*>(x) + i);

    float s  = (v.x + v.y) + (v.z + v.w);
    float mn = fminf(fminf(v.x, v.y), fminf(v.z, v.w));
    float mx = fmaxf(fmaxf(v.x, v.y), fmaxf(v.z, v.w));
#pragma unroll
    for (int o = 16; o > 0; o >>= 1) {
        s  += __shfl_down_sync(0xffffffffu, s, o);
        mn = fminf(mn, __shfl_down_sync(0xffffffffu, mn, o));
        mx = fmaxf(mx, __shfl_down_sync(0xffffffffu, mx, o));
    }
    __shared__ float sh_s[8], sh_mn[8], sh_mx[8];
    int w = threadIdx.x >> 5, l = threadIdx.x & 31;
    if (l == 0) { sh_s[w] = s; sh_mn[w] = mn; sh_mx[w] = mx; }
    __syncthreads();
    if (threadIdx.x == 0) {
        float S = 0.f, MN = CUDART_INF_F, MX = -CUDART_INF_F;
#pragma unroll
        for (int k = 0; k < 8; k++) {
            S += sh_s[k];
            MN = fminf(MN, sh_mn[k]);
            MX = fmaxf(MX, sh_mx[k]);
        }
        g_psum[blockIdx.x] = S;
        g_pmin[blockIdx.x] = MN;
        g_pmax[blockIdx.x] = MX;
    }
}

// ------------------------------------------------------------------
// Kernel 1b: fold the 4 partials per channel (fixed order, determ.).
// One thread per (b,c) channel.
// ------------------------------------------------------------------
__global__ void __launch_bounds__(256) k_stat2() {
    int c = blockIdx.x * 256 + threadIdx.x;   // channel index [0, BB*CC)
    int p = c * 4;
    float s  = ((g_psum[p] + g_psum[p + 1]) + (g_psum[p + 2] + g_psum[p + 3]));
    float mn = fminf(fminf(g_pmin[p], g_pmin[p + 1]), fminf(g_pmin[p + 2], g_pmin[p + 3]));
    float mx = fmaxf(fmaxf(g_pmax[p], g_pmax[p + 1]), fmaxf(g_pmax[p + 2], g_pmax[p + 3]));
    g_mean[c] = s * (1.0f / HW);
    g_min[c]  = mn;
    g_max[c]  = mx;
}

// ------------------------------------------------------------------
// Kernel 2: SE MLP + hardsigmoid scale per (b,c), and per-sample
// min/max of out = scale*x (scale>=0 => min(scale*x)=scale*min(x)).
// One block per batch sample, 256 threads (= C).
// ------------------------------------------------------------------
__global__ void k_se(const float* __restrict__ w1, const float* __restrict__ b1,
                     const float* __restrict__ w2, const float* __restrict__ b2) {
    int b = blockIdx.x, t = threadIdx.x;
    __shared__ float pooled[CC];
    __shared__ float hsh[CS];

    pooled[t] = g_mean[b * CC + t];
    __syncthreads();

    if (t < CS) {
        float acc = b1[t];
#pragma unroll 8
        for (int c = 0; c < CC; c++) acc = fmaf(pooled[c], w1[t * CC + c], acc);
        hsh[t] = fmaxf(acc, 0.f);
    }
    __syncthreads();

    float acc = b2[t];
#pragma unroll 8
    for (int s = 0; s < CS; s++) acc = fmaf(hsh[s], w2[t * CS + s], acc);
    float sc = fminf(fmaxf(acc / 6.0f + 0.5f, 0.f), 1.f);   // hardsigmoid
    g_scale[b * CC + t] = sc;

    float mn = sc * g_min[b * CC + t];
    float mx = sc * g_max[b * CC + t];
#pragma unroll
    for (int o = 16; o > 0; o >>= 1) {
        mn = fminf(mn, __shfl_down_sync(0xffffffffu, mn, o));
        mx = fmaxf(mx, __shfl_down_sync(0xffffffffu, mx, o));
    }
    __shared__ float sh_mn[8], sh_mx[8];
    int w = t >> 5, l = t & 31;
    if (l == 0) { sh_mn[w] = mn; sh_mx[w] = mx; }
    __syncthreads();
    if (t == 0) {
        float MN = CUDART_INF_F, MX = -CUDART_INF_F;
#pragma unroll
        for (int i = 0; i < 8; i++) { MN = fminf(MN, sh_mn[i]); MX = fmaxf(MX, sh_mx[i]); }
        g_smin[b] = MN;
        g_smax[b] = MX;
    }
}

// ------------------------------------------------------------------
// Kernel 3: per-cluster segment min/max, EMA range update, quant params,
// scattered back to per-sample s/z. One block.
// ------------------------------------------------------------------
__global__ void k_cluster(const float* __restrict__ act_range,
                          const int* __restrict__ scl) {
    __shared__ float cs[NC], cz[NC];
    int t = threadIdx.x;
    if (t < NC) {
        float mn = CUDART_INF_F, mx = -CUDART_INF_F;  // JAX segment_min/max identities
        for (int b = 0; b < BB; b++) {
            if (scl[b] == t) {
                mn = fminf(mn, g_smin[b]);
                mx = fmaxf(mx, g_smax[b]);
            }
        }
        float nm = act_range[t * 2 + 0] * 0.995f + mn * 0.005f;
        float nx = act_range[t * 2 + 1] * 0.995f + mx * 0.005f;
        float s = (nx - nm) / 255.0f;
        float z = -rintf(__fdiv_rn(nm, s));
        cs[t] = s;
        cz[t] = z;
    }
    __syncthreads();
    if (t < BB) {
        int k = scl[t];
        g_s[t] = cs[k];
        g_z[t] = cz[k];
    }
}

// ------------------------------------------------------------------
// Kernel 4: streaming fake-quant — measured-at-ceiling config
// (87.8us, 70.7% DRAM, occ 79.7%, regs 21). One float4 per thread.
// ------------------------------------------------------------------
__global__ void __launch_bounds__(256) k_quant(const float* __restrict__ x,
                                               float* __restrict__ out) {
    int i = blockIdx.x * blockDim.x + threadIdx.x;  // float4 index
    int bc = i >> 10;        // HW/4 = 1024 float4 per channel
    int b  = bc >> 8;        // CC = 256 channels per sample
    float sc = __ldg(&g_scale[bc]);
    float s  = __ldg(&g_s[b]);
    float z  = __ldg(&g_z[b]);

    float4 v = reinterpret_cast<const float4*>(x)[i];
    float4 r;
#define QUANT(a, o)                                                          \
    {                                                                        \
        float ov = sc * (a);                                                 \
        float q  = fminf(fmaxf(rintf(__fdiv_rn(ov, s) + z), 0.f), 255.f);    \
        (o) = (q - z) * s;                                                   \
    }
    QUANT(v.x, r.x)
    QUANT(v.y, r.y)
    QUANT(v.z, r.z)
    QUANT(v.w, r.w)
#undef QUANT
    reinterpret_cast<float4*>(out)[i] = r;
}

extern "C" void kernel_launch(void* const* d_in, const int* in_sizes, int n_in,
                              void* d_out, int out_size) {
    const float* x         = (const float*)d_in[0];
    const float* w1        = (const float*)d_in[1];
    const float* b1        = (const float*)d_in[2];
    const float* w2        = (const float*)d_in[3];
    const float* b2        = (const float*)d_in[4];
    const float* act_range = (const float*)d_in[5];
    const int*   scl       = (const int*)d_in[6];
    float* out = (float*)d_out;

    // Stage 1: k_quant-shaped partial reduce (65536 blocks, 1 f4/thread)
    k_stat1<<<NPART, 256>>>(x);
    // Stage 2: fold 4 partials per channel
    k_stat2<<<(BB * CC) / 256, 256>>>();
    k_se<<<BB, 256>>>(w1, b1, w2, b2);
    k_cluster<<<1, 64>>>(act_range, scl);
    // k_quant: unchanged measured-optimal config
    k_quant<<<(BB * CC * HW / 4) / 256, 256>>>(x, out);
}

// round 12
// speedup vs baseline: 1.1567x; 1.1567x over previous
#include <cuda_runtime.h>
#include <math_constants.h>

#define BB 64
#define CC 256
#define HW 4096
#define CS 64
#define NC 8

// ---- scratch (no allocations allowed) ----
__device__ float g_mean[BB * CC];
__device__ float g_min[BB * CC];
__device__ float g_max[BB * CC];
__device__ float g_scale[BB * CC];
__device__ float g_smin[BB];
__device__ float g_smax[BB];
__device__ float g_s[BB];
__device__ float g_z[BB];

// ------------------------------------------------------------------
// Kernel 1: per-(b,c) mean / min / max — exact R2 config (best
// measured total). One 256-thread block per channel, 4 float4/thread.
// ------------------------------------------------------------------
__global__ void k_stat(const float* __restrict__ x) {
    int bc = blockIdx.x;
    const float4* xp = reinterpret_cast<const float4*>(x) + (size_t)bc * (HW / 4);

    float s = 0.f, mn = CUDART_INF_F, mx = -CUDART_INF_F;
#pragma unroll 4
    for (int i = threadIdx.x; i < HW / 4; i += 256) {
        float4 v = __ldg(&xp[i]);
        s += (v.x + v.y) + (v.z + v.w);
        mn = fminf(mn, fminf(fminf(v.x, v.y), fminf(v.z, v.w)));
        mx = fmaxf(mx, fmaxf(fmaxf(v.x, v.y), fmaxf(v.z, v.w)));
    }
#pragma unroll
    for (int o = 16; o > 0; o >>= 1) {
        s  += __shfl_down_sync(0xffffffffu, s, o);
        mn = fminf(mn, __shfl_down_sync(0xffffffffu, mn, o));
        mx = fmaxf(mx, __shfl_down_sync(0xffffffffu, mx, o));
    }
    __shared__ float sh_s[8], sh_mn[8], sh_mx[8];
    int w = threadIdx.x >> 5, l = threadIdx.x & 31;
    if (l == 0) { sh_s[w] = s; sh_mn[w] = mn; sh_mx[w] = mx; }
    __syncthreads();
    if (threadIdx.x == 0) {
        float S = 0.f, MN = CUDART_INF_F, MX = -CUDART_INF_F;
#pragma unroll
        for (int i = 0; i < 8; i++) {
            S += sh_s[i];
            MN = fminf(MN, sh_mn[i]);
            MX = fmaxf(MX, sh_mx[i]);
        }
        g_mean[bc] = S * (1.0f / HW);
        g_min[bc]  = MN;
        g_max[bc]  = MX;
    }
}

// ------------------------------------------------------------------
// Kernel 2: SE MLP + hardsigmoid scale per (b,c), and per-sample
// min/max of out = scale*x (scale>=0 => min(scale*x)=scale*min(x)).
// One block per batch sample, 256 threads (= C).
// ------------------------------------------------------------------
__global__ void k_se(const float* __restrict__ w1, const float* __restrict__ b1,
                     const float* __restrict__ w2, const float* __restrict__ b2) {
    int b = blockIdx.x, t = threadIdx.x;
    __shared__ float pooled[CC];
    __shared__ float hsh[CS];

    pooled[t] = g_mean[b * CC + t];
    __syncthreads();

    if (t < CS) {
        float acc = b1[t];
#pragma unroll 8
        for (int c = 0; c < CC; c++) acc = fmaf(pooled[c], w1[t * CC + c], acc);
        hsh[t] = fmaxf(acc, 0.f);
    }
    __syncthreads();

    float acc = b2[t];
#pragma unroll 8
    for (int s = 0; s < CS; s++) acc = fmaf(hsh[s], w2[t * CS + s], acc);
    float sc = fminf(fmaxf(acc / 6.0f + 0.5f, 0.f), 1.f);   // hardsigmoid
    g_scale[b * CC + t] = sc;

    float mn = sc * g_min[b * CC + t];
    float mx = sc * g_max[b * CC + t];
#pragma unroll
    for (int o = 16; o > 0; o >>= 1) {
        mn = fminf(mn, __shfl_down_sync(0xffffffffu, mn, o));
        mx = fmaxf(mx, __shfl_down_sync(0xffffffffu, mx, o));
    }
    __shared__ float sh_mn[8], sh_mx[8];
    int w = t >> 5, l = t & 31;
    if (l == 0) { sh_mn[w] = mn; sh_mx[w] = mx; }
    __syncthreads();
    if (t == 0) {
        float MN = CUDART_INF_F, MX = -CUDART_INF_F;
#pragma unroll
        for (int i = 0; i < 8; i++) { MN = fminf(MN, sh_mn[i]); MX = fmaxf(MX, sh_mx[i]); }
        g_smin[b] = MN;
        g_smax[b] = MX;
    }
}

// ------------------------------------------------------------------
// Kernel 3: per-cluster segment min/max + EMA + quant params.
// FIXED: stage all per-sample data into shared with 64 parallel
// loads first (was: 8 threads x 128 serial DRAM-latency loads).
// ------------------------------------------------------------------
__global__ void k_cluster(const float* __restrict__ act_range,
                          const int* __restrict__ scl) {
    __shared__ float smn[BB], smx[BB];
    __shared__ int   scls[BB];
    __shared__ float cs[NC], cz[NC];
    int t = threadIdx.x;   // 64 threads

    smn[t]  = g_smin[t];
    smx[t]  = g_smax[t];
    scls[t] = scl[t];
    __syncthreads();

    if (t < NC) {
        float mn = CUDART_INF_F, mx = -CUDART_INF_F;  // JAX segment identities
#pragma unroll
        for (int b = 0; b < BB; b++) {
            if (scls[b] == t) {
                mn = fminf(mn, smn[b]);
                mx = fmaxf(mx, smx[b]);
            }
        }
        float nm = act_range[t * 2 + 0] * 0.995f + mn * 0.005f;
        float nx = act_range[t * 2 + 1] * 0.995f + mx * 0.005f;
        float s = (nx - nm) / 255.0f;
        float z = -rintf(__fdiv_rn(nm, s));
        cs[t] = s;
        cz[t] = z;
    }
    __syncthreads();
    {
        int k = scls[t];
        g_s[t] = cs[k];
        g_z[t] = cz[k];
    }
}

// ------------------------------------------------------------------
// Kernel 4: streaming fake-quant — measured-optimal launch config
// (regs 21, occ ~80%). ONE change: stores use __stcs (evict-first)
// so dirty out-lines flush within this kernel's window instead of
// contending with next replay's k_stat reads.
// ------------------------------------------------------------------
__global__ void __launch_bounds__(256) k_quant(const float* __restrict__ x,
                                               float* __restrict__ out) {
    int i = blockIdx.x * blockDim.x + threadIdx.x;  // float4 index
    int bc = i >> 10;        // HW/4 = 1024 float4 per channel
    int b  = bc >> 8;        // CC = 256 channels per sample
    float sc = __ldg(&g_scale[bc]);
    float s  = __ldg(&g_s[b]);
    float z  = __ldg(&g_z[b]);

    float4 v = reinterpret_cast<const float4*>(x)[i];
    float4 r;
#define QUANT(a, o)                                                          \
    {                                                                        \
        float ov = sc * (a);                                                 \
        float q  = fminf(fmaxf(rintf(__fdiv_rn(ov, s) + z), 0.f), 255.f);    \
        (o) = (q - z) * s;                                                   \
    }
    QUANT(v.x, r.x)
    QUANT(v.y, r.y)
    QUANT(v.z, r.z)
    QUANT(v.w, r.w)
#undef QUANT
    __stcs(reinterpret_cast<float4*>(out) + i, r);
}

extern "C" void kernel_launch(void* const* d_in, const int* in_sizes, int n_in,
                              void* d_out, int out_size) {
    const float* x         = (const float*)d_in[0];
    const float* w1        = (const float*)d_in[1];
    const float* b1        = (const float*)d_in[2];
    const float* w2        = (const float*)d_in[3];
    const float* b2        = (const float*)d_in[4];
    const float* act_range = (const float*)d_in[5];
    const int*   scl       = (const int*)d_in[6];
    float* out = (float*)d_out;

    k_stat<<<BB * CC, 256>>>(x);
    k_se<<<BB, 256>>>(w1, b1, w2, b2);
    k_cluster<<<1, 64>>>(act_range, scl);
    k_quant<<<(BB * CC * HW / 4) / 256, 256>>>(x, out);
}